// round 3
// baseline (speedup 1.0000x reference)
#include <cuda_runtime.h>
#include <cstdint>

#define N_  512
#define C_  128
#define NN_ (N_*N_)
#define TSLD 18               // float2 per smem row (16 k + pad) -> 144B row
#define TTILE (128*TSLD)      // float2 per 128-row tile stage

// scratch device globals
__device__ float  g_zn[(size_t)NN_*C_];
__device__ float  g_gt[(size_t)NN_*C_];
__device__ float  g_at[(size_t)NN_*C_];   // a, c-major [c][i*N+k]
__device__ float  g_bt[(size_t)NN_*C_];   // b, c-major [c][j*N+k]
__device__ float  g_ot[(size_t)NN_*C_];   // einsum out, c-major [c][i*N+j]
__device__ float  g_o [(size_t)NN_*C_];   // row-major o
__device__ float2 g_ws[6*C_*C_];          // pre-split weights (hi,lo)

// ---------------------------------------------------------------------------
__device__ __forceinline__ float sigf(float x) { return 1.f / (1.f + __expf(-x)); }

__device__ __forceinline__ float2 splitf(float x) {
    uint32_t hi, lo;
    asm("cvt.rna.tf32.f32 %0, %1;" : "=r"(hi) : "f"(x));
    float r = x - __uint_as_float(hi);
    asm("cvt.rna.tf32.f32 %0, %1;" : "=r"(lo) : "f"(r));
    return make_float2(__uint_as_float(hi), __uint_as_float(lo));
}

__device__ __forceinline__ void mma_tf32(float* c, const uint32_t* a, const uint32_t* b) {
    asm volatile(
        "mma.sync.aligned.m16n8k8.row.col.f32.tf32.tf32.f32 "
        "{%0,%1,%2,%3},{%4,%5,%6,%7},{%8,%9},{%0,%1,%2,%3};\n"
        : "+f"(c[0]), "+f"(c[1]), "+f"(c[2]), "+f"(c[3])
        : "r"(a[0]), "r"(a[1]), "r"(a[2]), "r"(a[3]), "r"(b[0]), "r"(b[1]));
}

__device__ __forceinline__ void cp16(void* dst, const void* src) {
    unsigned s = (unsigned)__cvta_generic_to_shared(dst);
    asm volatile("cp.async.cg.shared.global [%0], [%1], 16;\n" :: "r"(s), "l"(src));
}
__device__ __forceinline__ void cp_commit() { asm volatile("cp.async.commit_group;\n"); }
__device__ __forceinline__ void cp_wait0()  { asm volatile("cp.async.wait_group 0;\n"); }

// fragment helpers: load A frag (hi/lo) for one 16-row group from split smem
#define LOAD_AFRAG(ap, r, k0, tg, AH, AL) do {                                  \
    float2 v0 = (ap)[(r)*TSLD + (k0) + (tg)];                                   \
    float2 v1 = (ap)[((r)+8)*TSLD + (k0) + (tg)];                               \
    float2 v2 = (ap)[(r)*TSLD + (k0) + (tg) + 4];                               \
    float2 v3 = (ap)[((r)+8)*TSLD + (k0) + (tg) + 4];                           \
    AH[0]=__float_as_uint(v0.x); AL[0]=__float_as_uint(v0.y);                   \
    AH[1]=__float_as_uint(v1.x); AL[1]=__float_as_uint(v1.y);                   \
    AH[2]=__float_as_uint(v2.x); AL[2]=__float_as_uint(v2.y);                   \
    AH[3]=__float_as_uint(v3.x); AL[3]=__float_as_uint(v3.y);                   \
} while(0)

#define LOAD_BFRAG(bp, n, k0, tg, BH, BL) do {                                  \
    float2 u0 = (bp)[(n)*TSLD + (k0) + (tg)];                                   \
    float2 u1 = (bp)[(n)*TSLD + (k0) + (tg) + 4];                               \
    BH[0]=__float_as_uint(u0.x); BL[0]=__float_as_uint(u0.y);                   \
    BH[1]=__float_as_uint(u1.x); BL[1]=__float_as_uint(u1.y);                   \
} while(0)

// ---------------------------------------------------------------------------
// one-time weight split: W[128x128] fp32 -> (hi,lo) float2
// ---------------------------------------------------------------------------
__global__ __launch_bounds__(256) void split_w_kernel(
    const float* __restrict__ w0, const float* __restrict__ w1,
    const float* __restrict__ w2, const float* __restrict__ w3,
    const float* __restrict__ w4, const float* __restrict__ w5,
    float2* __restrict__ ws)
{
    int which = blockIdx.y;
    const float* w = which==0?w0 : which==1?w1 : which==2?w2 :
                     which==3?w3 : which==4?w4 : w5;
    int idx = blockIdx.x*256 + threadIdx.x;
    ws[which*C_*C_ + idx] = splitf(w[idx]);
}

// ---------------------------------------------------------------------------
// LayerNorm over C=128
// ---------------------------------------------------------------------------
__global__ __launch_bounds__(128) void ln_kernel(
    const float* __restrict__ x, const float* __restrict__ w,
    const float* __restrict__ b, float* __restrict__ y)
{
    size_t row = blockIdx.x;
    int c = threadIdx.x;
    float v = x[row*C_ + c];
    float s = v, s2 = v*v;
    #pragma unroll
    for (int o = 16; o; o >>= 1) {
        s  += __shfl_xor_sync(0xffffffffu, s, o);
        s2 += __shfl_xor_sync(0xffffffffu, s2, o);
    }
    __shared__ float sh[8];
    int wid = c >> 5;
    if ((c & 31) == 0) { sh[wid] = s; sh[wid + 4] = s2; }
    __syncthreads();
    s  = sh[0] + sh[1] + sh[2] + sh[3];
    s2 = sh[4] + sh[5] + sh[6] + sh[7];
    float mu  = s  * (1.0f / C_);
    float var = s2 * (1.0f / C_) - mu * mu;
    float inv = rsqrtf(var + 1e-5f);
    y[row*C_ + c] = (v - mu) * inv * w[c] + b[c];
}

// ---------------------------------------------------------------------------
// transpose: out[c][r] = in[r][c]
// ---------------------------------------------------------------------------
__global__ __launch_bounds__(256) void transpose_kernel(
    const float* __restrict__ in, float* __restrict__ out, int R, int C)
{
    __shared__ float tile[32][33];
    size_t c0 = (size_t)blockIdx.x * 32, r0 = (size_t)blockIdx.y * 32;
    int tx = threadIdx.x, ty = threadIdx.y;
    #pragma unroll
    for (int k = 0; k < 4; k++)
        tile[ty + k*8][tx] = in[(r0 + ty + k*8) * C + c0 + tx];
    __syncthreads();
    #pragma unroll
    for (int k = 0; k < 4; k++)
        out[(c0 + ty + k*8) * R + r0 + tx] = tile[tx][ty + k*8];
}

// ---------------------------------------------------------------------------
// proj_dual: Yc (c-major) = mask[row] * sigmoid(X@W1^T) * (X@W2^T)
// 256 thr, 8 warps (2M x 4N), warp tile 64x32, BK=16 (8 chunks).
// W1/W2 pre-split, cp.async; X reg-staged + split.
// ---------------------------------------------------------------------------
__global__ __launch_bounds__(256, 1) void proj_dual(
    const float* __restrict__ X, const float2* __restrict__ W1p,
    const float2* __restrict__ W2p, const float* __restrict__ mask,
    float* __restrict__ Yc)
{
    extern __shared__ float2 sm2[];
    float2* xs  = sm2;              // [2][TTILE]
    float2* w1s = sm2 + 2*TTILE;
    float2* w2s = sm2 + 4*TTILE;

    int t = threadIdx.x, warp = t>>5, lane = t&31, g = lane>>2, tg = lane&3;
    size_t row0 = (size_t)blockIdx.x * 128;
    int m0 = (warp & 1) * 64;
    int n0 = (warp >> 1) * 32;

    float4 ra[2];
    int sr = t >> 1, sk = (t & 1) * 8;

    auto ldgX = [&](int kc) {
        const float* p = X + (row0 + sr)*C_ + kc*16 + sk;
        ra[0] = *(const float4*)p;
        ra[1] = *(const float4*)(p + 4);
    };
    auto stsX = [&](int s) {
        float2* d = xs + s*TTILE + sr*TSLD + sk;
        #pragma unroll
        for (int i = 0; i < 2; i++) {
            float2 p0 = splitf(((float*)&ra[i])[0]);
            float2 p1 = splitf(((float*)&ra[i])[1]);
            float2 p2 = splitf(((float*)&ra[i])[2]);
            float2 p3 = splitf(((float*)&ra[i])[3]);
            *(float4*)(d + i*4)     = make_float4(p0.x,p0.y,p1.x,p1.y);
            *(float4*)(d + i*4 + 2) = make_float4(p2.x,p2.y,p3.x,p3.y);
        }
    };
    auto cpW = [&](int kc, int s) {
        #pragma unroll
        for (int i = 0; i < 4; i++) {
            int e = i*256 + t;          // 0..1023
            int n = e >> 3, j = e & 7;
            cp16(w1s + s*TTILE + n*TSLD + j*2, W1p + n*C_ + kc*16 + j*2);
            cp16(w2s + s*TTILE + n*TSLD + j*2, W2p + n*C_ + kc*16 + j*2);
        }
        cp_commit();
    };

    float acc1[4][4][4], acc2[4][4][4];
    #pragma unroll
    for (int mt=0; mt<4; mt++)
        #pragma unroll
        for (int nt=0; nt<4; nt++)
            #pragma unroll
            for (int q=0; q<4; q++) { acc1[mt][nt][q]=0.f; acc2[mt][nt][q]=0.f; }

    cpW(0, 0); ldgX(0);
    cp_wait0(); stsX(0);
    __syncthreads();

    #pragma unroll 1
    for (int kc = 0; kc < 8; kc++) {
        if (kc < 7) { cpW(kc+1, (kc+1)&1); ldgX(kc+1); }
        const float2* xp  = xs  + (kc&1)*TTILE;
        const float2* w1p = w1s + (kc&1)*TTILE;
        const float2* w2p = w2s + (kc&1)*TTILE;
        #pragma unroll
        for (int k0 = 0; k0 < 16; k0 += 8) {
            uint32_t Ah[4][4], Al[4][4];
            #pragma unroll
            for (int mt=0; mt<4; mt++) {
                int r = m0 + mt*16 + g;
                LOAD_AFRAG(xp, r, k0, tg, Ah[mt], Al[mt]);
            }
            #pragma unroll
            for (int nt=0; nt<4; nt++) {
                int n = n0 + nt*8 + g;
                uint32_t Bh[2], Bl[2];
                LOAD_BFRAG(w1p, n, k0, tg, Bh, Bl);
                #pragma unroll
                for (int mt=0; mt<4; mt++) {
                    mma_tf32(acc1[mt][nt], Ah[mt], Bh);
                    mma_tf32(acc1[mt][nt], Al[mt], Bh);
                    mma_tf32(acc1[mt][nt], Ah[mt], Bl);
                }
                LOAD_BFRAG(w2p, n, k0, tg, Bh, Bl);
                #pragma unroll
                for (int mt=0; mt<4; mt++) {
                    mma_tf32(acc2[mt][nt], Ah[mt], Bh);
                    mma_tf32(acc2[mt][nt], Al[mt], Bh);
                    mma_tf32(acc2[mt][nt], Ah[mt], Bl);
                }
            }
        }
        if (kc < 7) { cp_wait0(); stsX((kc+1)&1); }
        __syncthreads();
    }

    // epilogue: gate*proj into smem tile, then c-major coalesced store
    float* so = (float*)sm2;           // [128][130]
    #pragma unroll
    for (int mt=0; mt<4; mt++) {
        int rl = m0 + mt*16 + g, rh = rl + 8;
        float ml = mask[row0 + rl], mh = mask[row0 + rh];
        #pragma unroll
        for (int nt=0; nt<4; nt++) {
            int cl = n0 + nt*8 + 2*tg;
            so[rl*130 + cl]     = ml * sigf(acc1[mt][nt][0]) * acc2[mt][nt][0];
            so[rl*130 + cl + 1] = ml * sigf(acc1[mt][nt][1]) * acc2[mt][nt][1];
            so[rh*130 + cl]     = mh * sigf(acc1[mt][nt][2]) * acc2[mt][nt][2];
            so[rh*130 + cl + 1] = mh * sigf(acc1[mt][nt][3]) * acc2[mt][nt][3];
        }
    }
    __syncthreads();
    int c  = t >> 1;
    int rs = (t & 1) * 64;
    #pragma unroll
    for (int i = 0; i < 64; i += 4) {
        float4 v;
        v.x = so[(rs+i  )*130 + c];
        v.y = so[(rs+i+1)*130 + c];
        v.z = so[(rs+i+2)*130 + c];
        v.w = so[(rs+i+3)*130 + c];
        *(float4*)(Yc + (size_t)c*NN_ + row0 + rs + i) = v;
    }
}

// ---------------------------------------------------------------------------
// proj_single: MODE 1: Y = sigmoid(X@W^T); MODE 2: Y = extra .* (X@W^T)
// 128 thr, 4 warps (2M x 2N), warp tile 64x64, BK=16 (8 chunks).
// ---------------------------------------------------------------------------
template<int MODE>
__global__ __launch_bounds__(128, 2) void proj_single(
    const float* __restrict__ X, const float2* __restrict__ Wp,
    const float* __restrict__ extra, float* __restrict__ Y)
{
    extern __shared__ float2 sm2[];
    float2* xs = sm2;               // [2][TTILE]
    float2* ws = sm2 + 2*TTILE;

    int t = threadIdx.x, warp = t>>5, lane = t&31, g = lane>>2, tg = lane&3;
    size_t row0 = (size_t)blockIdx.x * 128;
    int m0 = (warp & 1) * 64;
    int n0 = (warp >> 1) * 64;

    float4 ra[4];
    auto ldgX = [&](int kc) {
        const float* p = X + (row0 + t)*C_ + kc*16;
        #pragma unroll
        for (int i=0;i<4;i++) ra[i] = *(const float4*)(p + i*4);
    };
    auto stsX = [&](int s) {
        float2* d = xs + s*TTILE + t*TSLD;
        #pragma unroll
        for (int i = 0; i < 4; i++) {
            float2 p0 = splitf(((float*)&ra[i])[0]);
            float2 p1 = splitf(((float*)&ra[i])[1]);
            float2 p2 = splitf(((float*)&ra[i])[2]);
            float2 p3 = splitf(((float*)&ra[i])[3]);
            *(float4*)(d + i*4)     = make_float4(p0.x,p0.y,p1.x,p1.y);
            *(float4*)(d + i*4 + 2) = make_float4(p2.x,p2.y,p3.x,p3.y);
        }
    };
    auto cpW = [&](int kc, int s) {
        #pragma unroll
        for (int i = 0; i < 8; i++) {
            int e = i*128 + t;
            int n = e >> 3, j = e & 7;
            cp16(ws + s*TTILE + n*TSLD + j*2, Wp + n*C_ + kc*16 + j*2);
        }
        cp_commit();
    };

    float acc[4][8][4];
    #pragma unroll
    for (int mt=0; mt<4; mt++)
        #pragma unroll
        for (int nt=0; nt<8; nt++)
            #pragma unroll
            for (int q=0; q<4; q++) acc[mt][nt][q]=0.f;

    cpW(0, 0); ldgX(0);
    cp_wait0(); stsX(0);
    __syncthreads();

    #pragma unroll 1
    for (int kc = 0; kc < 8; kc++) {
        if (kc < 7) { cpW(kc+1, (kc+1)&1); ldgX(kc+1); }
        const float2* xp = xs + (kc&1)*TTILE;
        const float2* wp = ws + (kc&1)*TTILE;
        #pragma unroll
        for (int k0 = 0; k0 < 16; k0 += 8) {
            uint32_t Ah[4][4], Al[4][4];
            #pragma unroll
            for (int mt=0; mt<4; mt++) {
                int r = m0 + mt*16 + g;
                LOAD_AFRAG(xp, r, k0, tg, Ah[mt], Al[mt]);
            }
            #pragma unroll
            for (int nt=0; nt<8; nt++) {
                int n = n0 + nt*8 + g;
                uint32_t Bh[2], Bl[2];
                LOAD_BFRAG(wp, n, k0, tg, Bh, Bl);
                #pragma unroll
                for (int mt=0; mt<4; mt++) {
                    mma_tf32(acc[mt][nt], Ah[mt], Bh);
                    mma_tf32(acc[mt][nt], Al[mt], Bh);
                    mma_tf32(acc[mt][nt], Ah[mt], Bl);
                }
            }
        }
        if (kc < 7) { cp_wait0(); stsX((kc+1)&1); }
        __syncthreads();
    }

    #pragma unroll
    for (int mt=0; mt<4; mt++) {
        size_t rl = row0 + m0 + mt*16 + g;
        size_t rh = rl + 8;
        #pragma unroll
        for (int nt=0; nt<8; nt++) {
            int cl = n0 + nt*8 + 2*tg;
            float2 v0, v1;
            if (MODE == 1) {
                v0 = make_float2(sigf(acc[mt][nt][0]), sigf(acc[mt][nt][1]));
                v1 = make_float2(sigf(acc[mt][nt][2]), sigf(acc[mt][nt][3]));
            } else {
                float2 el = *(const float2*)(extra + rl*C_ + cl);
                float2 eh = *(const float2*)(extra + rh*C_ + cl);
                v0 = make_float2(el.x*acc[mt][nt][0], el.y*acc[mt][nt][1]);
                v1 = make_float2(eh.x*acc[mt][nt][2], eh.y*acc[mt][nt][3]);
            }
            *(float2*)(Y + rl*C_ + cl) = v0;
            *(float2*)(Y + rh*C_ + cl) = v1;
        }
    }
}

// ---------------------------------------------------------------------------
// triangle einsum per channel: Ot[c][i][j] = sum_k At[c][i][k]*Bt[c][j][k]
// 128 thr, 4 warps (2M x 2N), warp tile 64x64, BK=16 (32 chunks), reg-split.
// ---------------------------------------------------------------------------
__global__ __launch_bounds__(128, 2) void tri_mma(
    const float* __restrict__ At, const float* __restrict__ Bt,
    float* __restrict__ Ot)
{
    extern __shared__ float2 sm2[];
    float2* as = sm2;               // [2][TTILE]
    float2* bs = sm2 + 2*TTILE;

    int t = threadIdx.x, warp = t>>5, lane = t&31, g = lane>>2, tg = lane&3;
    size_t coff = (size_t)blockIdx.z * NN_;
    const float* A = At + coff + (size_t)blockIdx.y * 128 * N_;
    const float* B = Bt + coff + (size_t)blockIdx.x * 128 * N_;
    int m0 = (warp & 1) * 64;
    int n0 = (warp >> 1) * 64;

    float4 ra[4], rb[4];
    auto ldg = [&](int kc) {
        const float* ap = A + (size_t)t*N_ + kc*16;
        const float* bp = B + (size_t)t*N_ + kc*16;
        #pragma unroll
        for (int i=0;i<4;i++) { ra[i] = *(const float4*)(ap+i*4); rb[i] = *(const float4*)(bp+i*4); }
    };
    auto sts = [&](int s) {
        float2* ad = as + s*TTILE + t*TSLD;
        float2* bd = bs + s*TTILE + t*TSLD;
        #pragma unroll
        for (int i = 0; i < 4; i++) {
            float2 p0 = splitf(((float*)&ra[i])[0]);
            float2 p1 = splitf(((float*)&ra[i])[1]);
            float2 p2 = splitf(((float*)&ra[i])[2]);
            float2 p3 = splitf(((float*)&ra[i])[3]);
            *(float4*)(ad + i*4)     = make_float4(p0.x,p0.y,p1.x,p1.y);
            *(float4*)(ad + i*4 + 2) = make_float4(p2.x,p2.y,p3.x,p3.y);
            float2 q0 = splitf(((float*)&rb[i])[0]);
            float2 q1 = splitf(((float*)&rb[i])[1]);
            float2 q2 = splitf(((float*)&rb[i])[2]);
            float2 q3 = splitf(((float*)&rb[i])[3]);
            *(float4*)(bd + i*4)     = make_float4(q0.x,q0.y,q1.x,q1.y);
            *(float4*)(bd + i*4 + 2) = make_float4(q2.x,q2.y,q3.x,q3.y);
        }
    };

    float acc[4][8][4];
    #pragma unroll
    for (int mt=0; mt<4; mt++)
        #pragma unroll
        for (int nt=0; nt<8; nt++)
            #pragma unroll
            for (int q=0; q<4; q++) acc[mt][nt][q]=0.f;

    ldg(0); sts(0);
    __syncthreads();

    #pragma unroll 1
    for (int kc = 0; kc < 32; kc++) {
        if (kc < 31) ldg(kc+1);
        const float2* ap = as + (kc&1)*TTILE;
        const float2* bp = bs + (kc&1)*TTILE;
        #pragma unroll
        for (int k0 = 0; k0 < 16; k0 += 8) {
            uint32_t Ah[4][4], Al[4][4];
            #pragma unroll
            for (int mt=0; mt<4; mt++) {
                int r = m0 + mt*16 + g;
                LOAD_AFRAG(ap, r, k0, tg, Ah[mt], Al[mt]);
            }
            #pragma unroll
            for (int nt=0; nt<8; nt++) {
                int n = n0 + nt*8 + g;
                uint32_t Bh[2], Bl[2];
                LOAD_BFRAG(bp, n, k0, tg, Bh, Bl);
                #pragma unroll
                for (int mt=0; mt<4; mt++) {
                    mma_tf32(acc[mt][nt], Ah[mt], Bh);
                    mma_tf32(acc[mt][nt], Al[mt], Bh);
                    mma_tf32(acc[mt][nt], Ah[mt], Bl);
                }
            }
        }
        if (kc < 31) sts((kc+1)&1);
        __syncthreads();
    }

    float* O = Ot + coff;
    int i_base = blockIdx.y * 128 + m0;
    int j_base = blockIdx.x * 128 + n0;
    #pragma unroll
    for (int mt=0; mt<4; mt++) {
        int r = i_base + mt*16 + g;
        #pragma unroll
        for (int nt=0; nt<8; nt++) {
            int cl = j_base + nt*8 + 2*tg;
            *(float2*)(O + (size_t)r*N_ + cl)     = make_float2(acc[mt][nt][0], acc[mt][nt][1]);
            *(float2*)(O + (size_t)(r+8)*N_ + cl) = make_float2(acc[mt][nt][2], acc[mt][nt][3]);
        }
    }
}

// ---------------------------------------------------------------------------
extern "C" void kernel_launch(void* const* d_in, const int* in_sizes, int n_in,
                              void* d_out, int out_size)
{
    const float* z      = (const float*)d_in[0];
    const float* mask   = (const float*)d_in[1];
    const float* ln_i_w = (const float*)d_in[2];
    const float* ln_i_b = (const float*)d_in[3];
    const float* ln_o_w = (const float*)d_in[4];
    const float* ln_o_b = (const float*)d_in[5];
    const float* w_pa   = (const float*)d_in[6];
    const float* w_pb   = (const float*)d_in[7];
    const float* w_ga   = (const float*)d_in[8];
    const float* w_gb   = (const float*)d_in[9];
    const float* w_g    = (const float*)d_in[10];
    const float* w_o    = (const float*)d_in[11];
    float* out = (float*)d_out;

    float *zn, *gt, *at, *bt, *ot, *o;
    float2* ws;
    cudaGetSymbolAddress((void**)&zn, g_zn);
    cudaGetSymbolAddress((void**)&gt, g_gt);
    cudaGetSymbolAddress((void**)&at, g_at);
    cudaGetSymbolAddress((void**)&bt, g_bt);
    cudaGetSymbolAddress((void**)&ot, g_ot);
    cudaGetSymbolAddress((void**)&o,  g_o);
    cudaGetSymbolAddress((void**)&ws, g_ws);
    float* on = zn;   // reuse: zn dead after projections

    const int SMEM_D = 6*TTILE*8;   // 110592
    const int SMEM_S = 4*TTILE*8;   // 73728
    cudaFuncSetAttribute(proj_dual,      cudaFuncAttributeMaxDynamicSharedMemorySize, SMEM_D);
    cudaFuncSetAttribute(proj_single<1>, cudaFuncAttributeMaxDynamicSharedMemorySize, SMEM_S);
    cudaFuncSetAttribute(proj_single<2>, cudaFuncAttributeMaxDynamicSharedMemorySize, SMEM_S);
    cudaFuncSetAttribute(tri_mma,        cudaFuncAttributeMaxDynamicSharedMemorySize, SMEM_S);

    // 0) pre-split all 6 weight matrices
    split_w_kernel<<<dim3(64, 6), 256>>>(w_ga, w_pa, w_gb, w_pb, w_g, w_o, ws);
    // 1) zn = LN(z)
    ln_kernel<<<NN_, 128>>>(z, ln_i_w, ln_i_b, zn);
    // 2) at = c-major( mask * sigmoid(zn@w_ga^T) * (zn@w_pa^T) )
    proj_dual<<<NN_/128, 256, SMEM_D>>>(zn, ws + 0*C_*C_, ws + 1*C_*C_, mask, at);
    // 3) bt = c-major( mask * sigmoid(zn@w_gb^T) * (zn@w_pb^T) )
    proj_dual<<<NN_/128, 256, SMEM_D>>>(zn, ws + 2*C_*C_, ws + 3*C_*C_, mask, bt);
    // 4) gate = sigmoid(zn@w_g^T)   (row-major)
    proj_single<1><<<NN_/128, 128, SMEM_S>>>(zn, ws + 4*C_*C_, nullptr, gt);
    // 5) Ot[c][i][j] = sum_k At[c][i][k]*Bt[c][j][k]
    tri_mma<<<dim3(N_/128, N_/128, C_), 128, SMEM_S>>>(at, bt, ot);
    // 6) o = row-major(ot)
    transpose_kernel<<<dim3(NN_/32, C_/32), dim3(32, 8)>>>(ot, o, C_, NN_);
    // 7) on = LN(o)
    ln_kernel<<<NN_, 128>>>(o, ln_o_w, ln_o_b, on);
    // 8) out = gate .* (on @ w_o^T)
    proj_single<2><<<NN_/128, 128, SMEM_S>>>(on, ws + 5*C_*C_, gt, out);
}

// round 4
// speedup vs baseline: 1.5270x; 1.5270x over previous
#include <cuda_runtime.h>
#include <cstdint>

#define N_  512
#define C_  128
#define NN_ (N_*N_)
#define KK_ 64                 // k-pairs per 128-length row
#define XLD 66                 // padded uint2 row for proj smem
#define TLD 18                 // padded uint2 row for tri smem (16 kk chunk)
#define SSTG (128*TLD)         // uint2 per tri stage per matrix

// scratch device globals (packed uint2 = (bf16x2 hi, bf16x2 lo) per k-pair)
__device__ uint2 g_znp[(size_t)NN_*KK_];        // LN(z) packed; reused for LN(o)
__device__ uint2 g_atp[(size_t)C_*(NN_/2)];     // a packed, c-major [c][r/2]
__device__ uint2 g_btp[(size_t)C_*(NN_/2)];     // b packed, c-major
__device__ float g_gt [(size_t)NN_*C_];         // gate fp32 row-major
__device__ float g_ot [(size_t)NN_*C_];         // einsum out, c-major
__device__ float g_o  [(size_t)NN_*C_];         // o row-major
__device__ uint2 g_wp [6*C_*KK_];               // packed weights [n][kk]

// ---------------------------------------------------------------------------
__device__ __forceinline__ float sigf(float x) { return 1.f / (1.f + __expf(-x)); }

// pack two fp32 into (hi bf16x2, lo bf16x2); low half of each reg = x0
__device__ __forceinline__ uint2 pack_split(float x0, float x1) {
    uint32_t h, l;
    asm("cvt.rn.bf16x2.f32 %0, %1, %2;" : "=r"(h) : "f"(x1), "f"(x0));
    float h0 = __uint_as_float(h << 16);
    float h1 = __uint_as_float(h & 0xffff0000u);
    float r0 = x0 - h0, r1 = x1 - h1;
    asm("cvt.rn.bf16x2.f32 %0, %1, %2;" : "=r"(l) : "f"(r1), "f"(r0));
    return make_uint2(h, l);
}

__device__ __forceinline__ void mma_bf16(float* c, const uint32_t* a, const uint32_t* b) {
    asm volatile(
        "mma.sync.aligned.m16n8k16.row.col.f32.bf16.bf16.f32 "
        "{%0,%1,%2,%3},{%4,%5,%6,%7},{%8,%9},{%0,%1,%2,%3};\n"
        : "+f"(c[0]), "+f"(c[1]), "+f"(c[2]), "+f"(c[3])
        : "r"(a[0]), "r"(a[1]), "r"(a[2]), "r"(a[3]), "r"(b[0]), "r"(b[1]));
}

__device__ __forceinline__ void cp16(void* dst, const void* src) {
    unsigned s = (unsigned)__cvta_generic_to_shared(dst);
    asm volatile("cp.async.cg.shared.global [%0], [%1], 16;\n" :: "r"(s), "l"(src));
}
__device__ __forceinline__ void cp_commit() { asm volatile("cp.async.commit_group;\n"); }

// A-frag (both planes) for one 16-row group: rows r,r+8; kk, kk+4
#define LDA(ap, ldk, r, kk, AH, AL) do {                 \
    uint2 v0 = (ap)[(r)*(ldk) + (kk)];                   \
    uint2 v1 = (ap)[((r)+8)*(ldk) + (kk)];               \
    uint2 v2 = (ap)[(r)*(ldk) + (kk) + 4];               \
    uint2 v3 = (ap)[((r)+8)*(ldk) + (kk) + 4];           \
    AH[0]=v0.x; AL[0]=v0.y; AH[1]=v1.x; AL[1]=v1.y;      \
    AH[2]=v2.x; AL[2]=v2.y; AH[3]=v3.x; AL[3]=v3.y;      \
} while(0)

#define LDB(bp, ldk, n, kk, BH, BL) do {                 \
    uint2 u0 = (bp)[(n)*(ldk) + (kk)];                   \
    uint2 u1 = (bp)[(n)*(ldk) + (kk) + 4];               \
    BH[0]=u0.x; BL[0]=u0.y; BH[1]=u1.x; BL[1]=u1.y;      \
} while(0)

#define MMA3(acc, AH, AL, BH, BL) do {                   \
    mma_bf16(acc, AH, BH);                               \
    mma_bf16(acc, AL, BH);                               \
    mma_bf16(acc, AH, BL);                               \
} while(0)

// ---------------------------------------------------------------------------
// one-time weight split: W[128x128] fp32 -> packed uint2 [n][kk]
// ---------------------------------------------------------------------------
__global__ __launch_bounds__(256) void split_w_kernel(
    const float* __restrict__ w0, const float* __restrict__ w1,
    const float* __restrict__ w2, const float* __restrict__ w3,
    const float* __restrict__ w4, const float* __restrict__ w5,
    uint2* __restrict__ wp)
{
    int which = blockIdx.y;
    const float* w = which==0?w0 : which==1?w1 : which==2?w2 :
                     which==3?w3 : which==4?w4 : w5;
    int idx = blockIdx.x*256 + threadIdx.x;      // 0..8191 pairs
    int n = idx >> 6, kk = idx & 63;
    wp[which*C_*KK_ + idx] = pack_split(w[n*C_ + kk*2], w[n*C_ + kk*2 + 1]);
}

// ---------------------------------------------------------------------------
// LayerNorm over C=128, output packed bf16 hi/lo
// ---------------------------------------------------------------------------
__global__ __launch_bounds__(128) void ln_pack_kernel(
    const float* __restrict__ x, const float* __restrict__ w,
    const float* __restrict__ b, uint2* __restrict__ yp)
{
    size_t row = blockIdx.x;
    int c = threadIdx.x;
    float v = x[row*C_ + c];
    float s = v, s2 = v*v;
    #pragma unroll
    for (int o = 16; o; o >>= 1) {
        s  += __shfl_xor_sync(0xffffffffu, s, o);
        s2 += __shfl_xor_sync(0xffffffffu, s2, o);
    }
    __shared__ float sh[8];
    int wid = c >> 5;
    if ((c & 31) == 0) { sh[wid] = s; sh[wid + 4] = s2; }
    __syncthreads();
    s  = sh[0] + sh[1] + sh[2] + sh[3];
    s2 = sh[4] + sh[5] + sh[6] + sh[7];
    float mu  = s  * (1.0f / C_);
    float var = s2 * (1.0f / C_) - mu * mu;
    float inv = rsqrtf(var + 1e-5f);
    float yv = (v - mu) * inv * w[c] + b[c];
    float yn = __shfl_down_sync(0xffffffffu, yv, 1);
    if ((c & 1) == 0)
        yp[row*KK_ + (c >> 1)] = pack_split(yv, yn);
}

// ---------------------------------------------------------------------------
// transpose: out[c][r] = in[r][c]
// ---------------------------------------------------------------------------
__global__ __launch_bounds__(256) void transpose_kernel(
    const float* __restrict__ in, float* __restrict__ out, int R, int C)
{
    __shared__ float tile[32][33];
    size_t c0 = (size_t)blockIdx.x * 32, r0 = (size_t)blockIdx.y * 32;
    int tx = threadIdx.x, ty = threadIdx.y;
    #pragma unroll
    for (int k = 0; k < 4; k++)
        tile[ty + k*8][tx] = in[(r0 + ty + k*8) * C + c0 + tx];
    __syncthreads();
    #pragma unroll
    for (int k = 0; k < 4; k++)
        out[(c0 + ty + k*8) * R + r0 + tx] = tile[tx][ty + k*8];
}

// ---------------------------------------------------------------------------
// proj_dual: Yc packed c-major = split( mask[r] * sigmoid(X@W1^T) * (X@W2^T) )
// 512 thr, 16 warps (4M x 4N), warp tile 32x32 per GEMM, K=128 resident.
// ---------------------------------------------------------------------------
__global__ __launch_bounds__(512, 1) void proj_dual(
    const uint2* __restrict__ Xp, const uint2* __restrict__ W1p,
    const uint2* __restrict__ W2p, const float* __restrict__ mask,
    uint2* __restrict__ Yp)
{
    extern __shared__ uint2 smu[];
    uint2* xs  = smu;                // [128][XLD]
    uint2* w1s = smu + 128*XLD;
    uint2* w2s = smu + 2*128*XLD;

    int t = threadIdx.x, warp = t>>5, lane = t&31, g = lane>>2, tg = lane&3;
    size_t row0 = (size_t)blockIdx.x * 128;
    int m0 = (warp & 3) * 32;
    int n0 = (warp >> 2) * 32;

    #pragma unroll
    for (int i = 0; i < 8; i++) {
        int e = i*512 + t;           // 0..4095, 16B chunks
        int r = e >> 5, q = (e & 31) * 2;
        cp16(xs  + r*XLD + q, Xp  + (row0 + r)*KK_ + q);
        cp16(w1s + r*XLD + q, W1p + r*KK_ + q);
        cp16(w2s + r*XLD + q, W2p + r*KK_ + q);
    }
    cp_commit();
    asm volatile("cp.async.wait_group 0;\n");
    __syncthreads();

    float acc1[2][4][4], acc2[2][4][4];
    #pragma unroll
    for (int mt=0; mt<2; mt++)
        #pragma unroll
        for (int nt=0; nt<4; nt++)
            #pragma unroll
            for (int q=0; q<4; q++) { acc1[mt][nt][q]=0.f; acc2[mt][nt][q]=0.f; }

    #pragma unroll
    for (int ks = 0; ks < 8; ks++) {
        int kb = ks*8 + tg;
        uint32_t Ah[2][4], Al[2][4];
        #pragma unroll
        for (int mt=0; mt<2; mt++) {
            int r = m0 + mt*16 + g;
            LDA(xs, XLD, r, kb, Ah[mt], Al[mt]);
        }
        #pragma unroll
        for (int nt=0; nt<4; nt++) {
            int n = n0 + nt*8 + g;
            uint32_t Bh[2], Bl[2];
            LDB(w1s, XLD, n, kb, Bh, Bl);
            #pragma unroll
            for (int mt=0; mt<2; mt++) MMA3(acc1[mt][nt], Ah[mt], Al[mt], Bh, Bl);
            LDB(w2s, XLD, n, kb, Bh, Bl);
            #pragma unroll
            for (int mt=0; mt<2; mt++) MMA3(acc2[mt][nt], Ah[mt], Al[mt], Bh, Bl);
        }
    }

    // epilogue: fp32 tile in smem, then packed c-major store
    __syncthreads();
    float* so = (float*)smu;        // [128][132]
    #pragma unroll
    for (int mt=0; mt<2; mt++) {
        int rl = m0 + mt*16 + g, rh = rl + 8;
        float ml = mask[row0 + rl], mh = mask[row0 + rh];
        #pragma unroll
        for (int nt=0; nt<4; nt++) {
            int cl = n0 + nt*8 + 2*tg;
            so[rl*132 + cl]     = ml * sigf(acc1[mt][nt][0]) * acc2[mt][nt][0];
            so[rl*132 + cl + 1] = ml * sigf(acc1[mt][nt][1]) * acc2[mt][nt][1];
            so[rh*132 + cl]     = mh * sigf(acc1[mt][nt][2]) * acc2[mt][nt][2];
            so[rh*132 + cl + 1] = mh * sigf(acc1[mt][nt][3]) * acc2[mt][nt][3];
        }
    }
    __syncthreads();
    int c  = t >> 2;
    int p0 = (t & 3) * 16;
    size_t base = (size_t)c * (NN_/2) + row0/2;
    #pragma unroll
    for (int p = 0; p < 16; p++) {
        int pr = p0 + p;
        Yp[base + pr] = pack_split(so[(2*pr)*132 + c], so[(2*pr+1)*132 + c]);
    }
}

// ---------------------------------------------------------------------------
// proj_single: MODE 1: Y = sigmoid(X@W^T); MODE 2: Y = extra .* (X@W^T)
// 512 thr, 16 warps (4M x 4N), warp tile 32x32, K=128 resident.
// ---------------------------------------------------------------------------
template<int MODE>
__global__ __launch_bounds__(512, 1) void proj_single(
    const uint2* __restrict__ Xp, const uint2* __restrict__ Wp,
    const float* __restrict__ extra, float* __restrict__ Y)
{
    extern __shared__ uint2 smu[];
    uint2* xs = smu;                 // [128][XLD]
    uint2* ws = smu + 128*XLD;

    int t = threadIdx.x, warp = t>>5, lane = t&31, g = lane>>2, tg = lane&3;
    size_t row0 = (size_t)blockIdx.x * 128;
    int m0 = (warp & 3) * 32;
    int n0 = (warp >> 2) * 32;

    #pragma unroll
    for (int i = 0; i < 8; i++) {
        int e = i*512 + t;
        int r = e >> 5, q = (e & 31) * 2;
        cp16(xs + r*XLD + q, Xp + (row0 + r)*KK_ + q);
        cp16(ws + r*XLD + q, Wp + r*KK_ + q);
    }
    cp_commit();
    asm volatile("cp.async.wait_group 0;\n");
    __syncthreads();

    float acc[2][4][4];
    #pragma unroll
    for (int mt=0; mt<2; mt++)
        #pragma unroll
        for (int nt=0; nt<4; nt++)
            #pragma unroll
            for (int q=0; q<4; q++) acc[mt][nt][q]=0.f;

    #pragma unroll
    for (int ks = 0; ks < 8; ks++) {
        int kb = ks*8 + tg;
        uint32_t Ah[2][4], Al[2][4];
        #pragma unroll
        for (int mt=0; mt<2; mt++) {
            int r = m0 + mt*16 + g;
            LDA(xs, XLD, r, kb, Ah[mt], Al[mt]);
        }
        #pragma unroll
        for (int nt=0; nt<4; nt++) {
            int n = n0 + nt*8 + g;
            uint32_t Bh[2], Bl[2];
            LDB(ws, XLD, n, kb, Bh, Bl);
            #pragma unroll
            for (int mt=0; mt<2; mt++) MMA3(acc[mt][nt], Ah[mt], Al[mt], Bh, Bl);
        }
    }

    #pragma unroll
    for (int mt=0; mt<2; mt++) {
        size_t rl = row0 + m0 + mt*16 + g;
        size_t rh = rl + 8;
        #pragma unroll
        for (int nt=0; nt<4; nt++) {
            int cl = n0 + nt*8 + 2*tg;
            float2 v0, v1;
            if (MODE == 1) {
                v0 = make_float2(sigf(acc[mt][nt][0]), sigf(acc[mt][nt][1]));
                v1 = make_float2(sigf(acc[mt][nt][2]), sigf(acc[mt][nt][3]));
            } else {
                float2 el = *(const float2*)(extra + rl*C_ + cl);
                float2 eh = *(const float2*)(extra + rh*C_ + cl);
                v0 = make_float2(el.x*acc[mt][nt][0], el.y*acc[mt][nt][1]);
                v1 = make_float2(eh.x*acc[mt][nt][2], eh.y*acc[mt][nt][3]);
            }
            *(float2*)(Y + rl*C_ + cl) = v0;
            *(float2*)(Y + rh*C_ + cl) = v1;
        }
    }
}

// ---------------------------------------------------------------------------
// triangle einsum per channel: Ot[c][i][j] = sum_k At[c][i][k]*Bt[c][j][k]
// 256 thr, 8 warps (2M x 4N), warp tile 64x32, chunks of 16 kk, double-buffer.
// ---------------------------------------------------------------------------
__global__ __launch_bounds__(256, 2) void tri_mma(
    const uint2* __restrict__ Atp, const uint2* __restrict__ Btp,
    float* __restrict__ Ot)
{
    extern __shared__ uint2 smu[];
    uint2* as = smu;                 // [2][128][TLD]
    uint2* bs = smu + 2*SSTG;

    int t = threadIdx.x, warp = t>>5, lane = t&31, g = lane>>2, tg = lane&3;
    size_t coff2 = (size_t)blockIdx.z * (NN_/2);
    const uint2* A = Atp + coff2 + (size_t)blockIdx.y * 128 * (N_/2);
    const uint2* B = Btp + coff2 + (size_t)blockIdx.x * 128 * (N_/2);
    int m0 = (warp & 1) * 64;
    int n0 = (warp >> 1) * 32;

    auto stage = [&](int ch, int s) {
        uint2* ad = as + s*SSTG;
        uint2* bd = bs + s*SSTG;
        #pragma unroll
        for (int i = 0; i < 4; i++) {
            int e = i*256 + t;       // 0..1023 16B chunks per matrix
            int r = e >> 3, q = (e & 7) * 2;
            cp16(ad + r*TLD + q, A + (size_t)r*(N_/2) + ch*16 + q);
            cp16(bd + r*TLD + q, B + (size_t)r*(N_/2) + ch*16 + q);
        }
        cp_commit();
    };

    float acc[4][4][4];
    #pragma unroll
    for (int mt=0; mt<4; mt++)
        #pragma unroll
        for (int nt=0; nt<4; nt++)
            #pragma unroll
            for (int q=0; q<4; q++) acc[mt][nt][q]=0.f;

    stage(0, 0);
    #pragma unroll 1
    for (int ch = 0; ch < 16; ch++) {
        if (ch < 15) {
            stage(ch + 1, (ch + 1) & 1);
            asm volatile("cp.async.wait_group 1;\n");
        } else {
            asm volatile("cp.async.wait_group 0;\n");
        }
        __syncthreads();
        const uint2* ap = as + (ch & 1)*SSTG;
        const uint2* bp = bs + (ch & 1)*SSTG;
        #pragma unroll
        for (int ks = 0; ks < 2; ks++) {
            int kb = ks*8 + tg;
            uint32_t Ah[4][4], Al[4][4];
            #pragma unroll
            for (int mt=0; mt<4; mt++) {
                int r = m0 + mt*16 + g;
                LDA(ap, TLD, r, kb, Ah[mt], Al[mt]);
            }
            #pragma unroll
            for (int nt=0; nt<4; nt++) {
                int n = n0 + nt*8 + g;
                uint32_t Bh[2], Bl[2];
                LDB(bp, TLD, n, kb, Bh, Bl);
                #pragma unroll
                for (int mt=0; mt<4; mt++) MMA3(acc[mt][nt], Ah[mt], Al[mt], Bh, Bl);
            }
        }
        __syncthreads();
    }

    float* O = Ot + (size_t)blockIdx.z * NN_;
    int ib = blockIdx.y * 128 + m0;
    int jb = blockIdx.x * 128 + n0;
    #pragma unroll
    for (int mt=0; mt<4; mt++) {
        int r = ib + mt*16 + g;
        #pragma unroll
        for (int nt=0; nt<4; nt++) {
            int cl = jb + nt*8 + 2*tg;
            *(float2*)(O + (size_t)r*N_ + cl)     = make_float2(acc[mt][nt][0], acc[mt][nt][1]);
            *(float2*)(O + (size_t)(r+8)*N_ + cl) = make_float2(acc[mt][nt][2], acc[mt][nt][3]);
        }
    }
}

// ---------------------------------------------------------------------------
extern "C" void kernel_launch(void* const* d_in, const int* in_sizes, int n_in,
                              void* d_out, int out_size)
{
    const float* z      = (const float*)d_in[0];
    const float* mask   = (const float*)d_in[1];
    const float* ln_i_w = (const float*)d_in[2];
    const float* ln_i_b = (const float*)d_in[3];
    const float* ln_o_w = (const float*)d_in[4];
    const float* ln_o_b = (const float*)d_in[5];
    // weight order in g_wp: ga, pa, gb, pb, g, o
    const float* w_pa   = (const float*)d_in[6];
    const float* w_pb   = (const float*)d_in[7];
    const float* w_ga   = (const float*)d_in[8];
    const float* w_gb   = (const float*)d_in[9];
    const float* w_g    = (const float*)d_in[10];
    const float* w_o    = (const float*)d_in[11];
    float* out = (float*)d_out;

    uint2 *znp, *atp, *btp, *wp;
    float *gt, *ot, *o;
    cudaGetSymbolAddress((void**)&znp, g_znp);
    cudaGetSymbolAddress((void**)&atp, g_atp);
    cudaGetSymbolAddress((void**)&btp, g_btp);
    cudaGetSymbolAddress((void**)&gt,  g_gt);
    cudaGetSymbolAddress((void**)&ot,  g_ot);
    cudaGetSymbolAddress((void**)&o,   g_o);
    cudaGetSymbolAddress((void**)&wp,  g_wp);
    uint2* onp = znp;   // reuse: znp dead after projections

    const int SMEM_D = 3*128*XLD*8;   // 202752
    const int SMEM_S = 2*128*XLD*8;   // 135168
    const int SMEM_T = 4*SSTG*8;      // 73728
    cudaFuncSetAttribute(proj_dual,      cudaFuncAttributeMaxDynamicSharedMemorySize, SMEM_D);
    cudaFuncSetAttribute(proj_single<1>, cudaFuncAttributeMaxDynamicSharedMemorySize, SMEM_S);
    cudaFuncSetAttribute(proj_single<2>, cudaFuncAttributeMaxDynamicSharedMemorySize, SMEM_S);
    cudaFuncSetAttribute(tri_mma,        cudaFuncAttributeMaxDynamicSharedMemorySize, SMEM_T);

    // 0) pre-split weights into packed bf16 hi/lo
    split_w_kernel<<<dim3(32, 6), 256>>>(w_ga, w_pa, w_gb, w_pb, w_g, w_o, wp);
    // 1) znp = packed LN(z)
    ln_pack_kernel<<<NN_, 128>>>(z, ln_i_w, ln_i_b, znp);
    // 2) atp = packed c-major( mask * sigmoid(zn@w_ga^T) * (zn@w_pa^T) )
    proj_dual<<<NN_/128, 512, SMEM_D>>>(znp, wp + 0*C_*KK_, wp + 1*C_*KK_, mask, atp);
    // 3) btp = packed c-major( mask * sigmoid(zn@w_gb^T) * (zn@w_pb^T) )
    proj_dual<<<NN_/128, 512, SMEM_D>>>(znp, wp + 2*C_*KK_, wp + 3*C_*KK_, mask, btp);
    // 4) gate = sigmoid(zn@w_g^T)  fp32 row-major
    proj_single<1><<<NN_/128, 512, SMEM_S>>>(znp, wp + 4*C_*KK_, nullptr, gt);
    // 5) Ot[c][i][j] = sum_k At[c][i][k]*Bt[c][j][k]
    tri_mma<<<dim3(N_/128, N_/128, C_), 256, SMEM_T>>>(atp, btp, ot);
    // 6) o = row-major(ot)
    transpose_kernel<<<dim3(NN_/32, C_/32), dim3(32, 8)>>>(ot, o, C_, NN_);
    // 7) onp = packed LN(o)
    ln_pack_kernel<<<NN_, 128>>>(o, ln_o_w, ln_o_b, onp);
    // 8) out = gate .* (on @ w_o^T)
    proj_single<2><<<NN_/128, 512, SMEM_S>>>(onp, wp + 5*C_*KK_, gt, out);
}

// round 5
// speedup vs baseline: 1.5326x; 1.0037x over previous
#include <cuda_runtime.h>
#include <cstdint>

#define N_  512
#define C_  128
#define NN_ (N_*N_)
#define KK_ 64                 // k-pairs per 128-length row
#define XLD 66                 // padded uint2 row for proj smem
#define TLD 18                 // padded uint2 row for tri smem (16 kk chunk)
#define SSTG (128*TLD)         // uint2 per tri stage per matrix

// scratch device globals (packed uint2 = (bf16x2 hi, bf16x2 lo) per k-pair)
__device__ uint2 g_znp[(size_t)NN_*KK_];        // LN(z) packed; reused for LN(o)
__device__ uint2 g_atp[(size_t)C_*(NN_/2)];     // a packed, c-major [c][r/2]
__device__ uint2 g_btp[(size_t)C_*(NN_/2)];     // b packed, c-major
__device__ float g_gt [(size_t)NN_*C_];         // gate fp32 row-major
__device__ float g_ot [(size_t)NN_*C_];         // einsum out, c-major
__device__ float g_o  [(size_t)NN_*C_];         // o row-major
__device__ uint2 g_wp [6*C_*KK_];               // packed weights [n][kk]

// ---------------------------------------------------------------------------
__device__ __forceinline__ float sigf(float x) { return 1.f / (1.f + __expf(-x)); }

// pack two fp32 into (hi bf16x2, lo bf16x2); low half of each reg = x0
__device__ __forceinline__ uint2 pack_split(float x0, float x1) {
    uint32_t h, l;
    asm("cvt.rn.bf16x2.f32 %0, %1, %2;" : "=r"(h) : "f"(x1), "f"(x0));
    float h0 = __uint_as_float(h << 16);
    float h1 = __uint_as_float(h & 0xffff0000u);
    float r0 = x0 - h0, r1 = x1 - h1;
    asm("cvt.rn.bf16x2.f32 %0, %1, %2;" : "=r"(l) : "f"(r1), "f"(r0));
    return make_uint2(h, l);
}

__device__ __forceinline__ void mma_bf16(float* c, const uint32_t* a, const uint32_t* b) {
    asm volatile(
        "mma.sync.aligned.m16n8k16.row.col.f32.bf16.bf16.f32 "
        "{%0,%1,%2,%3},{%4,%5,%6,%7},{%8,%9},{%0,%1,%2,%3};\n"
        : "+f"(c[0]), "+f"(c[1]), "+f"(c[2]), "+f"(c[3])
        : "r"(a[0]), "r"(a[1]), "r"(a[2]), "r"(a[3]), "r"(b[0]), "r"(b[1]));
}

__device__ __forceinline__ void cp16(void* dst, const void* src) {
    unsigned s = (unsigned)__cvta_generic_to_shared(dst);
    asm volatile("cp.async.cg.shared.global [%0], [%1], 16;\n" :: "r"(s), "l"(src));
}
__device__ __forceinline__ void cp_commit() { asm volatile("cp.async.commit_group;\n"); }

// A-frag (both planes) for one 16-row group: rows r,r+8; kk, kk+4
#define LDA(ap, ldk, r, kk, AH, AL) do {                 \
    uint2 v0 = (ap)[(r)*(ldk) + (kk)];                   \
    uint2 v1 = (ap)[((r)+8)*(ldk) + (kk)];               \
    uint2 v2 = (ap)[(r)*(ldk) + (kk) + 4];               \
    uint2 v3 = (ap)[((r)+8)*(ldk) + (kk) + 4];           \
    AH[0]=v0.x; AL[0]=v0.y; AH[1]=v1.x; AL[1]=v1.y;      \
    AH[2]=v2.x; AL[2]=v2.y; AH[3]=v3.x; AL[3]=v3.y;      \
} while(0)

#define LDB(bp, ldk, n, kk, BH, BL) do {                 \
    uint2 u0 = (bp)[(n)*(ldk) + (kk)];                   \
    uint2 u1 = (bp)[(n)*(ldk) + (kk) + 4];               \
    BH[0]=u0.x; BL[0]=u0.y; BH[1]=u1.x; BL[1]=u1.y;      \
} while(0)

#define MMA3(acc, AH, AL, BH, BL) do {                   \
    mma_bf16(acc, AH, BH);                               \
    mma_bf16(acc, AL, BH);                               \
    mma_bf16(acc, AH, BL);                               \
} while(0)

// ---------------------------------------------------------------------------
// one-time weight split: W[128x128] fp32 -> packed uint2 [n][kk]
// ---------------------------------------------------------------------------
__global__ __launch_bounds__(256) void split_w_kernel(
    const float* __restrict__ w0, const float* __restrict__ w1,
    const float* __restrict__ w2, const float* __restrict__ w3,
    const float* __restrict__ w4, const float* __restrict__ w5,
    uint2* __restrict__ wp)
{
    int which = blockIdx.y;
    const float* w = which==0?w0 : which==1?w1 : which==2?w2 :
                     which==3?w3 : which==4?w4 : w5;
    int idx = blockIdx.x*256 + threadIdx.x;      // 0..8191 pairs
    int n = idx >> 6, kk = idx & 63;
    wp[which*C_*KK_ + idx] = pack_split(w[n*C_ + kk*2], w[n*C_ + kk*2 + 1]);
}

// ---------------------------------------------------------------------------
// LayerNorm over C=128, output packed bf16 hi/lo
// ---------------------------------------------------------------------------
__global__ __launch_bounds__(128) void ln_pack_kernel(
    const float* __restrict__ x, const float* __restrict__ w,
    const float* __restrict__ b, uint2* __restrict__ yp)
{
    size_t row = blockIdx.x;
    int c = threadIdx.x;
    float v = x[row*C_ + c];
    float s = v, s2 = v*v;
    #pragma unroll
    for (int o = 16; o; o >>= 1) {
        s  += __shfl_xor_sync(0xffffffffu, s, o);
        s2 += __shfl_xor_sync(0xffffffffu, s2, o);
    }
    __shared__ float sh[8];
    int wid = c >> 5;
    if ((c & 31) == 0) { sh[wid] = s; sh[wid + 4] = s2; }
    __syncthreads();
    s  = sh[0] + sh[1] + sh[2] + sh[3];
    s2 = sh[4] + sh[5] + sh[6] + sh[7];
    float mu  = s  * (1.0f / C_);
    float var = s2 * (1.0f / C_) - mu * mu;
    float inv = rsqrtf(var + 1e-5f);
    float yv = (v - mu) * inv * w[c] + b[c];
    float yn = __shfl_down_sync(0xffffffffu, yv, 1);
    if ((c & 1) == 0)
        yp[row*KK_ + (c >> 1)] = pack_split(yv, yn);
}

// ---------------------------------------------------------------------------
// transpose: out[c][r] = in[r][c]
// ---------------------------------------------------------------------------
__global__ __launch_bounds__(256) void transpose_kernel(
    const float* __restrict__ in, float* __restrict__ out, int R, int C)
{
    __shared__ float tile[32][33];
    size_t c0 = (size_t)blockIdx.x * 32, r0 = (size_t)blockIdx.y * 32;
    int tx = threadIdx.x, ty = threadIdx.y;
    #pragma unroll
    for (int k = 0; k < 4; k++)
        tile[ty + k*8][tx] = in[(r0 + ty + k*8) * C + c0 + tx];
    __syncthreads();
    #pragma unroll
    for (int k = 0; k < 4; k++)
        out[(c0 + ty + k*8) * R + r0 + tx] = tile[tx][ty + k*8];
}

// ---------------------------------------------------------------------------
// proj_dual: Yc packed c-major = split( mask[r] * sigmoid(X@W1^T) * (X@W2^T) )
// 512 thr, 16 warps (4M x 4N), warp tile 32x32 per GEMM, K=128 resident.
// ---------------------------------------------------------------------------
__global__ __launch_bounds__(512, 1) void proj_dual(
    const uint2* __restrict__ Xp, const uint2* __restrict__ W1p,
    const uint2* __restrict__ W2p, const float* __restrict__ mask,
    uint2* __restrict__ Yp)
{
    extern __shared__ uint2 smu[];
    uint2* xs  = smu;                // [128][XLD]
    uint2* w1s = smu + 128*XLD;
    uint2* w2s = smu + 2*128*XLD;

    int t = threadIdx.x, warp = t>>5, lane = t&31, g = lane>>2, tg = lane&3;
    size_t row0 = (size_t)blockIdx.x * 128;
    int m0 = (warp & 3) * 32;
    int n0 = (warp >> 2) * 32;

    #pragma unroll
    for (int i = 0; i < 8; i++) {
        int e = i*512 + t;           // 0..4095, 16B chunks
        int r = e >> 5, q = (e & 31) * 2;
        cp16(xs  + r*XLD + q, Xp  + (row0 + r)*KK_ + q);
        cp16(w1s + r*XLD + q, W1p + r*KK_ + q);
        cp16(w2s + r*XLD + q, W2p + r*KK_ + q);
    }
    cp_commit();
    asm volatile("cp.async.wait_group 0;\n");
    __syncthreads();

    float acc1[2][4][4], acc2[2][4][4];
    #pragma unroll
    for (int mt=0; mt<2; mt++)
        #pragma unroll
        for (int nt=0; nt<4; nt++)
            #pragma unroll
            for (int q=0; q<4; q++) { acc1[mt][nt][q]=0.f; acc2[mt][nt][q]=0.f; }

    #pragma unroll
    for (int ks = 0; ks < 8; ks++) {
        int kb = ks*8 + tg;
        uint32_t Ah[2][4], Al[2][4];
        #pragma unroll
        for (int mt=0; mt<2; mt++) {
            int r = m0 + mt*16 + g;
            LDA(xs, XLD, r, kb, Ah[mt], Al[mt]);
        }
        #pragma unroll
        for (int nt=0; nt<4; nt++) {
            int n = n0 + nt*8 + g;
            uint32_t Bh[2], Bl[2];
            LDB(w1s, XLD, n, kb, Bh, Bl);
            #pragma unroll
            for (int mt=0; mt<2; mt++) MMA3(acc1[mt][nt], Ah[mt], Al[mt], Bh, Bl);
            LDB(w2s, XLD, n, kb, Bh, Bl);
            #pragma unroll
            for (int mt=0; mt<2; mt++) MMA3(acc2[mt][nt], Ah[mt], Al[mt], Bh, Bl);
        }
    }

    // epilogue: fp32 tile in smem, then packed c-major store
    __syncthreads();
    float* so = (float*)smu;        // [128][132]
    #pragma unroll
    for (int mt=0; mt<2; mt++) {
        int rl = m0 + mt*16 + g, rh = rl + 8;
        float ml = mask[row0 + rl], mh = mask[row0 + rh];
        #pragma unroll
        for (int nt=0; nt<4; nt++) {
            int cl = n0 + nt*8 + 2*tg;
            so[rl*132 + cl]     = ml * sigf(acc1[mt][nt][0]) * acc2[mt][nt][0];
            so[rl*132 + cl + 1] = ml * sigf(acc1[mt][nt][1]) * acc2[mt][nt][1];
            so[rh*132 + cl]     = mh * sigf(acc1[mt][nt][2]) * acc2[mt][nt][2];
            so[rh*132 + cl + 1] = mh * sigf(acc1[mt][nt][3]) * acc2[mt][nt][3];
        }
    }
    __syncthreads();
    int c  = t >> 2;
    int p0 = (t & 3) * 16;
    size_t base = (size_t)c * (NN_/2) + row0/2;
    #pragma unroll
    for (int p = 0; p < 16; p++) {
        int pr = p0 + p;
        Yp[base + pr] = pack_split(so[(2*pr)*132 + c], so[(2*pr+1)*132 + c]);
    }
}

// ---------------------------------------------------------------------------
// proj_single: MODE 1: Y = sigmoid(X@W^T); MODE 2: Y = extra .* (X@W^T)
// 512 thr, 16 warps (4M x 4N), warp tile 32x32, K=128 resident.
// ---------------------------------------------------------------------------
template<int MODE>
__global__ __launch_bounds__(512, 1) void proj_single(
    const uint2* __restrict__ Xp, const uint2* __restrict__ Wp,
    const float* __restrict__ extra, float* __restrict__ Y)
{
    extern __shared__ uint2 smu[];
    uint2* xs = smu;                 // [128][XLD]
    uint2* ws = smu + 128*XLD;

    int t = threadIdx.x, warp = t>>5, lane = t&31, g = lane>>2, tg = lane&3;
    size_t row0 = (size_t)blockIdx.x * 128;
    int m0 = (warp & 3) * 32;
    int n0 = (warp >> 2) * 32;

    #pragma unroll
    for (int i = 0; i < 8; i++) {
        int e = i*512 + t;
        int r = e >> 5, q = (e & 31) * 2;
        cp16(xs + r*XLD + q, Xp + (row0 + r)*KK_ + q);
        cp16(ws + r*XLD + q, Wp + r*KK_ + q);
    }
    cp_commit();
    asm volatile("cp.async.wait_group 0;\n");
    __syncthreads();

    float acc[2][4][4];
    #pragma unroll
    for (int mt=0; mt<2; mt++)
        #pragma unroll
        for (int nt=0; nt<4; nt++)
            #pragma unroll
            for (int q=0; q<4; q++) acc[mt][nt][q]=0.f;

    #pragma unroll
    for (int ks = 0; ks < 8; ks++) {
        int kb = ks*8 + tg;
        uint32_t Ah[2][4], Al[2][4];
        #pragma unroll
        for (int mt=0; mt<2; mt++) {
            int r = m0 + mt*16 + g;
            LDA(xs, XLD, r, kb, Ah[mt], Al[mt]);
        }
        #pragma unroll
        for (int nt=0; nt<4; nt++) {
            int n = n0 + nt*8 + g;
            uint32_t Bh[2], Bl[2];
            LDB(ws, XLD, n, kb, Bh, Bl);
            #pragma unroll
            for (int mt=0; mt<2; mt++) MMA3(acc[mt][nt], Ah[mt], Al[mt], Bh, Bl);
        }
    }

    #pragma unroll
    for (int mt=0; mt<2; mt++) {
        size_t rl = row0 + m0 + mt*16 + g;
        size_t rh = rl + 8;
        #pragma unroll
        for (int nt=0; nt<4; nt++) {
            int cl = n0 + nt*8 + 2*tg;
            float2 v0, v1;
            if (MODE == 1) {
                v0 = make_float2(sigf(acc[mt][nt][0]), sigf(acc[mt][nt][1]));
                v1 = make_float2(sigf(acc[mt][nt][2]), sigf(acc[mt][nt][3]));
            } else {
                float2 el = *(const float2*)(extra + rl*C_ + cl);
                float2 eh = *(const float2*)(extra + rh*C_ + cl);
                v0 = make_float2(el.x*acc[mt][nt][0], el.y*acc[mt][nt][1]);
                v1 = make_float2(eh.x*acc[mt][nt][2], eh.y*acc[mt][nt][3]);
            }
            *(float2*)(Y + rl*C_ + cl) = v0;
            *(float2*)(Y + rh*C_ + cl) = v1;
        }
    }
}

// ---------------------------------------------------------------------------
// triangle einsum per channel: Ot[c][i][j] = sum_k At[c][i][k]*Bt[c][j][k]
// 256 thr, 8 warps (2M x 4N), warp tile 64x32, chunks of 16 kk, double-buffer.
// ---------------------------------------------------------------------------
__global__ __launch_bounds__(256, 2) void tri_mma(
    const uint2* __restrict__ Atp, const uint2* __restrict__ Btp,
    float* __restrict__ Ot)
{
    extern __shared__ uint2 smu[];
    uint2* as = smu;                 // [2][128][TLD]
    uint2* bs = smu + 2*SSTG;

    int t = threadIdx.x, warp = t>>5, lane = t&31, g = lane>>2, tg = lane&3;
    size_t coff2 = (size_t)blockIdx.z * (NN_/2);
    const uint2* A = Atp + coff2 + (size_t)blockIdx.y * 128 * (N_/2);
    const uint2* B = Btp + coff2 + (size_t)blockIdx.x * 128 * (N_/2);
    int m0 = (warp & 1) * 64;
    int n0 = (warp >> 1) * 32;

    auto stage = [&](int ch, int s) {
        uint2* ad = as + s*SSTG;
        uint2* bd = bs + s*SSTG;
        #pragma unroll
        for (int i = 0; i < 4; i++) {
            int e = i*256 + t;       // 0..1023 16B chunks per matrix
            int r = e >> 3, q = (e & 7) * 2;
            cp16(ad + r*TLD + q, A + (size_t)r*(N_/2) + ch*16 + q);
            cp16(bd + r*TLD + q, B + (size_t)r*(N_/2) + ch*16 + q);
        }
        cp_commit();
    };

    float acc[4][4][4];
    #pragma unroll
    for (int mt=0; mt<4; mt++)
        #pragma unroll
        for (int nt=0; nt<4; nt++)
            #pragma unroll
            for (int q=0; q<4; q++) acc[mt][nt][q]=0.f;

    stage(0, 0);
    #pragma unroll 1
    for (int ch = 0; ch < 16; ch++) {
        if (ch < 15) {
            stage(ch + 1, (ch + 1) & 1);
            asm volatile("cp.async.wait_group 1;\n");
        } else {
            asm volatile("cp.async.wait_group 0;\n");
        }
        __syncthreads();
        const uint2* ap = as + (ch & 1)*SSTG;
        const uint2* bp = bs + (ch & 1)*SSTG;
        #pragma unroll
        for (int ks = 0; ks < 2; ks++) {
            int kb = ks*8 + tg;
            uint32_t Ah[4][4], Al[4][4];
            #pragma unroll
            for (int mt=0; mt<4; mt++) {
                int r = m0 + mt*16 + g;
                LDA(ap, TLD, r, kb, Ah[mt], Al[mt]);
            }
            #pragma unroll
            for (int nt=0; nt<4; nt++) {
                int n = n0 + nt*8 + g;
                uint32_t Bh[2], Bl[2];
                LDB(bp, TLD, n, kb, Bh, Bl);
                #pragma unroll
                for (int mt=0; mt<4; mt++) MMA3(acc[mt][nt], Ah[mt], Al[mt], Bh, Bl);
            }
        }
        __syncthreads();
    }

    float* O = Ot + (size_t)blockIdx.z * NN_;
    int ib = blockIdx.y * 128 + m0;
    int jb = blockIdx.x * 128 + n0;
    #pragma unroll
    for (int mt=0; mt<4; mt++) {
        int r = ib + mt*16 + g;
        #pragma unroll
        for (int nt=0; nt<4; nt++) {
            int cl = jb + nt*8 + 2*tg;
            *(float2*)(O + (size_t)r*N_ + cl)     = make_float2(acc[mt][nt][0], acc[mt][nt][1]);
            *(float2*)(O + (size_t)(r+8)*N_ + cl) = make_float2(acc[mt][nt][2], acc[mt][nt][3]);
        }
    }
}

// ---------------------------------------------------------------------------
extern "C" void kernel_launch(void* const* d_in, const int* in_sizes, int n_in,
                              void* d_out, int out_size)
{
    const float* z      = (const float*)d_in[0];
    const float* mask   = (const float*)d_in[1];
    const float* ln_i_w = (const float*)d_in[2];
    const float* ln_i_b = (const float*)d_in[3];
    const float* ln_o_w = (const float*)d_in[4];
    const float* ln_o_b = (const float*)d_in[5];
    // weight order in g_wp: ga, pa, gb, pb, g, o
    const float* w_pa   = (const float*)d_in[6];
    const float* w_pb   = (const float*)d_in[7];
    const float* w_ga   = (const float*)d_in[8];
    const float* w_gb   = (const float*)d_in[9];
    const float* w_g    = (const float*)d_in[10];
    const float* w_o    = (const float*)d_in[11];
    float* out = (float*)d_out;

    uint2 *znp, *atp, *btp, *wp;
    float *gt, *ot, *o;
    cudaGetSymbolAddress((void**)&znp, g_znp);
    cudaGetSymbolAddress((void**)&atp, g_atp);
    cudaGetSymbolAddress((void**)&btp, g_btp);
    cudaGetSymbolAddress((void**)&gt,  g_gt);
    cudaGetSymbolAddress((void**)&ot,  g_ot);
    cudaGetSymbolAddress((void**)&o,   g_o);
    cudaGetSymbolAddress((void**)&wp,  g_wp);
    uint2* onp = znp;   // reuse: znp dead after projections

    const int SMEM_D = 3*128*XLD*8;   // 202752
    const int SMEM_S = 2*128*XLD*8;   // 135168
    const int SMEM_T = 4*SSTG*8;      // 73728
    cudaFuncSetAttribute(proj_dual,      cudaFuncAttributeMaxDynamicSharedMemorySize, SMEM_D);
    cudaFuncSetAttribute(proj_single<1>, cudaFuncAttributeMaxDynamicSharedMemorySize, SMEM_S);
    cudaFuncSetAttribute(proj_single<2>, cudaFuncAttributeMaxDynamicSharedMemorySize, SMEM_S);
    cudaFuncSetAttribute(tri_mma,        cudaFuncAttributeMaxDynamicSharedMemorySize, SMEM_T);

    // 0) pre-split weights into packed bf16 hi/lo
    split_w_kernel<<<dim3(32, 6), 256>>>(w_ga, w_pa, w_gb, w_pb, w_g, w_o, wp);
    // 1) znp = packed LN(z)
    ln_pack_kernel<<<NN_, 128>>>(z, ln_i_w, ln_i_b, znp);
    // 2) atp = packed c-major( mask * sigmoid(zn@w_ga^T) * (zn@w_pa^T) )
    proj_dual<<<NN_/128, 512, SMEM_D>>>(znp, wp + 0*C_*KK_, wp + 1*C_*KK_, mask, atp);
    // 3) btp = packed c-major( mask * sigmoid(zn@w_gb^T) * (zn@w_pb^T) )
    proj_dual<<<NN_/128, 512, SMEM_D>>>(znp, wp + 2*C_*KK_, wp + 3*C_*KK_, mask, btp);
    // 4) gate = sigmoid(zn@w_g^T)  fp32 row-major
    proj_single<1><<<NN_/128, 512, SMEM_S>>>(znp, wp + 4*C_*KK_, nullptr, gt);
    // 5) Ot[c][i][j] = sum_k At[c][i][k]*Bt[c][j][k]
    tri_mma<<<dim3(N_/128, N_/128, C_), 256, SMEM_T>>>(atp, btp, ot);
    // 6) o = row-major(ot)
    transpose_kernel<<<dim3(NN_/32, C_/32), dim3(32, 8)>>>(ot, o, C_, NN_);
    // 7) onp = packed LN(o)
    ln_pack_kernel<<<NN_, 128>>>(o, ln_o_w, ln_o_b, onp);
    // 8) out = gate .* (on @ w_o^T)
    proj_single<2><<<NN_/128, 512, SMEM_S>>>(onp, wp + 5*C_*KK_, gt, out);
}